// round 14
// baseline (speedup 1.0000x reference)
#include <cuda_runtime.h>
#include <cuda_fp16.h>
#include <math.h>
#include <stdint.h>

// Problem constants (B=2048, A=32, D=128, H=256)
#define NB    2048
#define NA    32
#define NROWS (NB * NA)   // 65536
#define DIN   128
#define HD    256
#define H3    768
#define H4    1024

// ---------------------------------------------------------------------------
// Scratch
// ---------------------------------------------------------------------------
__device__ float g_sg [(size_t)NB * H3];
__device__ float g_bias2[H4];
__device__ float g_zero_bias[H3];   // never written -> stays zero

__device__ uint4 g_gh_f  [(size_t)NROWS * H3 / 8];
__device__ uint4 g_gc2_f [(size_t)NROWS * H4 / 8];   // [rz-combined 512 | Gih_n 256 | h_n 256]
__device__ uint4 g_obs_f [(size_t)NROWS * DIN / 8];
__device__ uint4 g_e_f   [(size_t)NROWS * HD / 8];
__device__ uint4 g_hh_f  [(size_t)NROWS * HD / 8];
__device__ uint4 g_h1_f  [(size_t)NROWS * HD / 8];
__device__ uint4 g_S_f   [(size_t)NB * HD / 8];
__device__ uint4 g_ew_f  [(size_t)HD * DIN / 8];
__device__ uint4 g_fw_f  [(size_t)HD * HD / 8];
__device__ uint4 g_wih_f [(size_t)H3 * HD / 8];
__device__ uint4 g_whh_f [(size_t)H3 * HD / 8];
__device__ uint4 g_wc2_f [(size_t)H4 * HD / 8];      // combined weight for gcat2

__device__ __forceinline__ float sigmoidf_(float x) { return 1.0f / (1.0f + expf(-x)); }

__device__ __forceinline__ uint32_t smem_to_u32(const void* p) {
    uint32_t a;
    asm("{ .reg .u64 t; cvta.to.shared.u64 t, %1; cvt.u32.u64 %0, t; }" : "=r"(a) : "l"(p));
    return a;
}

#define SMEM_SWIZZLE_128B(off) ((off) ^ (((off) >> 3) & 0x70))

// ---------------------------------------------------------------------------
// primitives
// ---------------------------------------------------------------------------
__device__ __forceinline__ void mma_f16(float* c, uint32_t a0, uint32_t a1, uint32_t a2,
                                        uint32_t a3, uint32_t b0, uint32_t b1) {
    asm volatile(
        "mma.sync.aligned.m16n8k16.row.col.f32.f16.f16.f32 "
        "{%0,%1,%2,%3}, {%4,%5,%6,%7}, {%8,%9}, {%0,%1,%2,%3};"
        : "+f"(c[0]), "+f"(c[1]), "+f"(c[2]), "+f"(c[3])
        : "r"(a0), "r"(a1), "r"(a2), "r"(a3), "r"(b0), "r"(b1));
}
__device__ __forceinline__ void ldm_x4(uint32_t* r, uint32_t addr) {
    asm volatile("ldmatrix.sync.aligned.m8n8.x4.shared.b16 {%0,%1,%2,%3}, [%4];"
                 : "=r"(r[0]), "=r"(r[1]), "=r"(r[2]), "=r"(r[3]) : "r"(addr));
}
__device__ __forceinline__ void ldm_x2(uint32_t* r, uint32_t addr) {
    asm volatile("ldmatrix.sync.aligned.m8n8.x2.shared.b16 {%0,%1}, [%2];"
                 : "=r"(r[0]), "=r"(r[1]) : "r"(addr));
}
__device__ __forceinline__ void cp16(uint32_t dst, const void* src) {
    asm volatile("cp.async.cg.shared.global [%0], [%1], 16;" :: "r"(dst), "l"(src));
}
#define CP_COMMIT()  asm volatile("cp.async.commit_group;")
#define CP_WAIT(n)   asm volatile("cp.async.wait_group %0;" :: "n"(n))

__device__ __forceinline__ uint32_t pack_h2(float a, float b) {
    __half2 h = __floats2half2_rn(a, b);
    return *reinterpret_cast<uint32_t*>(&h);
}
__device__ __forceinline__ float4 h4_to_f4(uint2 u) {
    float2 fa = __half22float2(*reinterpret_cast<__half2*>(&u.x));
    float2 fb = __half22float2(*reinterpret_cast<__half2*>(&u.y));
    return make_float4(fa.x, fa.y, fb.x, fb.y);
}

// ---------------------------------------------------------------------------
// conversions
// ---------------------------------------------------------------------------
__global__ void convert_h(const float4* __restrict__ src, uint2* __restrict__ dst, int n4)
{
    const int i = blockIdx.x * blockDim.x + threadIdx.x;
    if (i >= n4) return;
    float4 v = src[i];
    uint2 o;
    o.x = pack_h2(v.x, v.y);
    o.y = pack_h2(v.z, v.w);
    dst[i] = o;
}

// All weight conversions in one launch (float4 units):
//  [0,8192)        ew -> ew_f
//  [8192,24576)    fw -> fw_f
//  [24576,73728)   wih -> wih_f
//  [73728,122880)  whh -> whh_f
//  [122880,155648) combined rz: whh[i] - wih[i]/32 -> wc2_f[0:32768)
//  [155648,172032) wih rows 512..767 -> wc2_f[32768:49152)
//  [172032,188416) whh rows 512..767 -> wc2_f[49152:65536)
__global__ void convert_weights(const float4* __restrict__ ew, const float4* __restrict__ fw,
                                const float4* __restrict__ wih, const float4* __restrict__ whh,
                                uint2* __restrict__ ew_f, uint2* __restrict__ fw_f,
                                uint2* __restrict__ wih_f, uint2* __restrict__ whh_f,
                                uint2* __restrict__ wc2_f)
{
    const int gid = blockIdx.x * blockDim.x + threadIdx.x;
    float4 v;
    uint2* dst;
    int i;
    if (gid < 8192)        { i = gid;          v = ew[i];  dst = ew_f + i; }
    else if (gid < 24576)  { i = gid - 8192;   v = fw[i];  dst = fw_f + i; }
    else if (gid < 73728)  { i = gid - 24576;  v = wih[i]; dst = wih_f + i; }
    else if (gid < 122880) { i = gid - 73728;  v = whh[i]; dst = whh_f + i; }
    else if (gid < 155648) {
        i = gid - 122880;
        float4 a = whh[i], b = wih[i];
        v.x = a.x - b.x * 0.03125f;  v.y = a.y - b.y * 0.03125f;
        v.z = a.z - b.z * 0.03125f;  v.w = a.w - b.w * 0.03125f;
        dst = wc2_f + i;
    }
    else if (gid < 172032) { i = gid - 155648; v = wih[32768 + i]; dst = wc2_f + 32768 + i; }
    else if (gid < 188416) { i = gid - 172032; v = whh[32768 + i]; dst = wc2_f + 49152 + i; }
    else return;
    uint2 o;
    o.x = pack_h2(v.x, v.y);
    o.y = pack_h2(v.z, v.w);
    *dst = o;
}

// bias2[1024]: [b_ih+b_hh (512) | 0 (256) | b_hh[512..768) (256)]
__global__ void bias2_kernel(const float* __restrict__ b_ih, const float* __restrict__ b_hh,
                             float* __restrict__ bias2)
{
    const int i = blockIdx.x * blockDim.x + threadIdx.x;
    if (i >= H4) return;
    float v;
    if (i < 512)      v = b_ih[i] + b_hh[i];
    else if (i < 768) v = 0.f;
    else              v = b_hh[i - 256];
    bias2[i] = v;
}

// ---------------------------------------------------------------------------
// fp16 GEMM, wide tile: CTA 128x256, KC=64, 3 stages (144KB), 1 CTA/SM.
// 8 warps (2m x 4n), warp tile 64x64 -> 1.0 LDS-wavefront per mma.
// cp.async 3-stage, 1 sync/chunk, ks-level fragment double-buffer.
// Requires N%128==0, M%256==0, K%64==0.
// ---------------------------------------------------------------------------
#define ST_AH 0
#define ST_WH 16384
#define ST_SZ 49152
#define SM_TOTAL (3 * ST_SZ)

template <bool RELU, bool WF32, bool WHALF>
__global__ __launch_bounds__(256, 1)
void mma_gemmh(const __half* __restrict__ Ag, const __half* __restrict__ Wg,
               const float* __restrict__ bias, float* __restrict__ C,
               __half* __restrict__ Ch, int K, int M)
{
    extern __shared__ char smem[];
    const uint32_t sb = smem_to_u32(smem);
    const int tid  = threadIdx.x;
    const int wid  = tid >> 5;
    const int lane = tid & 31;
    const int row0 = blockIdx.y * 128;
    const int col0 = blockIdx.x * 256;
    const int wm0  = (wid >> 2) * 64;   // 0 or 64
    const int wn0  = (wid & 3) * 64;    // 0,64,128,192

    const int a_row = wm0 + (lane & 15);
    const int a_kb  = ((lane >> 4) & 1) * 16;
    const int b_row = wn0 + (lane & 7);
    const int b_kb  = ((lane >> 3) & 1) * 16;

    // tile-load mapping: 32 rows per 256-thread pass; A 4 passes, W 8 passes.
    const int r0_ = tid >> 3, k00 = (tid & 7) * 8;
    const uint32_t sw0 = SMEM_SWIZZLE_128B((uint32_t)(r0_ * 128 + k00 * 2));
    const __half* pA0 = Ag + (size_t)(row0 + r0_) * K + k00;
    const __half* pW0 = Wg + (size_t)(col0 + r0_) * K + k00;
    const size_t itK = (size_t)32 * K;

    float acc[4][8][4];
#pragma unroll
    for (int i = 0; i < 4; i++)
#pragma unroll
        for (int j = 0; j < 8; j++)
#pragma unroll
            for (int q = 0; q < 4; q++) acc[i][j][q] = 0.f;

    const int nch = K >> 6;

    // prologue: prefetch chunks 0 and 1
#pragma unroll
    for (int it = 0; it < 4; it++) cp16(sb + ST_AH + sw0 + it * 4096, pA0 + it * itK);
#pragma unroll
    for (int it = 0; it < 8; it++) cp16(sb + ST_WH + sw0 + it * 4096, pW0 + it * itK);
    CP_COMMIT();
    if (nch > 1) {
#pragma unroll
        for (int it = 0; it < 4; it++)
            cp16(sb + ST_SZ + ST_AH + sw0 + it * 4096, pA0 + it * itK + 64);
#pragma unroll
        for (int it = 0; it < 8; it++)
            cp16(sb + ST_SZ + ST_WH + sw0 + it * 4096, pW0 + it * itK + 64);
    }
    CP_COMMIT();

    uint32_t Af[2][4][4], Bf[2][8][2];

    for (int ch = 0; ch < nch; ch++) {
        const uint32_t sbase = sb + (uint32_t)(ch % 3) * ST_SZ;
        if (ch + 1 < nch) { CP_WAIT(1); } else { CP_WAIT(0); }
        __syncthreads();
        if (ch + 2 < nch) {
            const uint32_t nbase = sb + (uint32_t)((ch + 2) % 3) * ST_SZ;
            const int koff = (ch + 2) * 64;
#pragma unroll
            for (int it = 0; it < 4; it++)
                cp16(nbase + ST_AH + sw0 + it * 4096, pA0 + it * itK + koff);
#pragma unroll
            for (int it = 0; it < 8; it++)
                cp16(nbase + ST_WH + sw0 + it * 4096, pW0 + it * itK + koff);
            CP_COMMIT();
        } else {
            CP_COMMIT();
        }

        // preload fragments for ks=0
#pragma unroll
        for (int fm = 0; fm < 4; fm++) {
            uint32_t loc = SMEM_SWIZZLE_128B((uint32_t)((a_row + fm * 16) * 128 + a_kb));
            ldm_x4(Af[0][fm], sbase + ST_AH + loc);
        }
#pragma unroll
        for (int fn = 0; fn < 8; fn++) {
            uint32_t loc = SMEM_SWIZZLE_128B((uint32_t)((b_row + fn * 8) * 128 + b_kb));
            ldm_x2(Bf[0][fn], sbase + ST_WH + loc);
        }

#pragma unroll
        for (int ks = 0; ks < 4; ks++) {
            const int cur = ks & 1, nxt = cur ^ 1;
            if (ks < 3) {
#pragma unroll
                for (int fm = 0; fm < 4; fm++) {
                    uint32_t loc = SMEM_SWIZZLE_128B(
                        (uint32_t)((a_row + fm * 16) * 128 + (ks + 1) * 32 + a_kb));
                    ldm_x4(Af[nxt][fm], sbase + ST_AH + loc);
                }
#pragma unroll
                for (int fn = 0; fn < 8; fn++) {
                    uint32_t loc = SMEM_SWIZZLE_128B(
                        (uint32_t)((b_row + fn * 8) * 128 + (ks + 1) * 32 + b_kb));
                    ldm_x2(Bf[nxt][fn], sbase + ST_WH + loc);
                }
            }
#pragma unroll
            for (int fm = 0; fm < 4; fm++)
#pragma unroll
                for (int fn = 0; fn < 8; fn++)
                    mma_f16(acc[fm][fn], Af[cur][fm][0], Af[cur][fm][1], Af[cur][fm][2],
                            Af[cur][fm][3], Bf[cur][fn][0], Bf[cur][fn][1]);
        }
    }

    const int gid  = lane >> 2;
    const int tid4 = lane & 3;
#pragma unroll
    for (int fn = 0; fn < 8; fn++) {
        const int col = col0 + wn0 + fn * 8 + 2 * tid4;
        const float b0 = bias[col], b1 = bias[col + 1];
#pragma unroll
        for (int fm = 0; fm < 4; fm++) {
            const int rlo = row0 + wm0 + fm * 16 + gid;
            float2 v0, v1;
            v0.x = acc[fm][fn][0] + b0;  v0.y = acc[fm][fn][1] + b1;
            v1.x = acc[fm][fn][2] + b0;  v1.y = acc[fm][fn][3] + b1;
            if (RELU) {
                v0.x = fmaxf(v0.x, 0.f); v0.y = fmaxf(v0.y, 0.f);
                v1.x = fmaxf(v1.x, 0.f); v1.y = fmaxf(v1.y, 0.f);
            }
            if (WF32) {
                *reinterpret_cast<float2*>(C + (size_t)rlo * M + col)       = v0;
                *reinterpret_cast<float2*>(C + (size_t)(rlo + 8) * M + col) = v1;
            }
            if (WHALF) {
                *reinterpret_cast<uint32_t*>(Ch + (size_t)rlo * M + col)       = pack_h2(v0.x, v0.y);
                *reinterpret_cast<uint32_t*>(Ch + (size_t)(rlo + 8) * M + col) = pack_h2(v1.x, v1.y);
            }
        }
    }
}

// ---------------------------------------------------------------------------
// GRU gates k=0 + per-batch agent sum (fp16 in/out, fp32 math).
// ---------------------------------------------------------------------------
__global__ void gates0S_kernel(const __half* __restrict__ gh,
                               const float* __restrict__ b_ih,
                               const __half* __restrict__ h_f,
                               __half* __restrict__ h1_f,
                               __half* __restrict__ S_f)
{
    const int b = blockIdx.x;
    const int j = threadIdx.x;
    const __half* ghb = gh  + (size_t)b * NA * H3;
    const __half* hb  = h_f + (size_t)b * NA * HD;
    __half* h1fb      = h1_f + (size_t)b * NA * HD;
    const float bir = b_ih[j], biz = b_ih[HD + j], bin = b_ih[2 * HD + j];
    float s = 0.f;
    for (int a = 0; a < NA; a++) {
        float gr = __half2float(ghb[a * H3 + j]);
        float gz = __half2float(ghb[a * H3 + HD + j]);
        float gn = __half2float(ghb[a * H3 + 2 * HD + j]);
        float hh = __half2float(hb[a * HD + j]);
        float r = sigmoidf_(bir + gr), z = sigmoidf_(biz + gz);
        float n = tanhf(bin + r * gn);
        float o = (1.f - z) * n + z * hh;
        h1fb[a * HD + j] = __float2half_rn(o);
        s += o;
    }
    S_f[(size_t)b * HD + j] = __float2half_rn(s);
}

// ---------------------------------------------------------------------------
// GRU gates k=1 + decoder, combined-rz formulation.
// gc2 row layout (fp16, 1024): [rz (512) | Gih_n (256) | h_n (256, incl b_hh_n)]
// ---------------------------------------------------------------------------
__global__ void gates1_dec_kernel(const __half* __restrict__ gc2,
                                  const float* __restrict__ Sg,
                                  const float* __restrict__ b_ih,
                                  const __half* __restrict__ h1_f,
                                  const float* __restrict__ dec_W,
                                  const float* __restrict__ dec_b,
                                  float* __restrict__ out)
{
    const int tid = threadIdx.x;
    const int i = blockIdx.x * 4 + (tid >> 6);
    const int b = i >> 5;
    const int q = tid & 63;
    const uint2*  gc = reinterpret_cast<const uint2*>(gc2 + (size_t)i * H4);
    const float4* sg = reinterpret_cast<const float4*>(Sg + (size_t)b * H3);
    const float4* bi = reinterpret_cast<const float4*>(b_ih);
    const float inv = 1.f / (float)NA;

    float4 rzr  = h4_to_f4(gc[q]);
    float4 rzz  = h4_to_f4(gc[64 + q]);
    float4 gihn = h4_to_f4(gc[128 + q]);
    float4 hn   = h4_to_f4(gc[192 + q]);
    float4 sg_r = sg[q], sg_z = sg[64 + q], sg_n = sg[128 + q];
    float4 bi_n = bi[128 + q];

    float4 hp = h4_to_f4(reinterpret_cast<const uint2*>(h1_f)[(size_t)i * 64 + q]);
    float4 dw = reinterpret_cast<const float4*>(dec_W)[q];

    float p = 0.f;
    { float r = sigmoidf_(rzr.x + sg_r.x * inv), z = sigmoidf_(rzz.x + sg_z.x * inv);
      float n = tanhf((sg_n.x - gihn.x) * inv + bi_n.x + r * hn.x);
      p += ((1.f - z) * n + z * hp.x) * dw.x; }
    { float r = sigmoidf_(rzr.y + sg_r.y * inv), z = sigmoidf_(rzz.y + sg_z.y * inv);
      float n = tanhf((sg_n.y - gihn.y) * inv + bi_n.y + r * hn.y);
      p += ((1.f - z) * n + z * hp.y) * dw.y; }
    { float r = sigmoidf_(rzr.z + sg_r.z * inv), z = sigmoidf_(rzz.z + sg_z.z * inv);
      float n = tanhf((sg_n.z - gihn.z) * inv + bi_n.z + r * hn.z);
      p += ((1.f - z) * n + z * hp.z) * dw.z; }
    { float r = sigmoidf_(rzr.w + sg_r.w * inv), z = sigmoidf_(rzz.w + sg_z.w * inv);
      float n = tanhf((sg_n.w - gihn.w) * inv + bi_n.w + r * hn.w);
      p += ((1.f - z) * n + z * hp.w) * dw.w; }
#pragma unroll
    for (int o = 16; o > 0; o >>= 1) p += __shfl_down_sync(0xffffffffu, p, o);
    __shared__ float red[8];
    if ((tid & 31) == 0) red[tid >> 5] = p;
    __syncthreads();
    if (tid < 4) out[blockIdx.x * 4 + tid] = red[2 * tid] + red[2 * tid + 1] + dec_b[0];
}

// ---------------------------------------------------------------------------
// Launch
// ---------------------------------------------------------------------------
extern "C" void kernel_launch(void* const* d_in, const int* in_sizes, int n_in,
                              void* d_out, int out_size)
{
    const float* obs    = (const float*)d_in[0];
    const float* enc_W  = (const float*)d_in[2];
    const float* enc_b  = (const float*)d_in[3];
    const float* fobs_W = (const float*)d_in[4];
    const float* fobs_b = (const float*)d_in[5];
    const float* W_ih   = (const float*)d_in[6];
    const float* b_ih   = (const float*)d_in[7];
    const float* W_hh   = (const float*)d_in[8];
    const float* b_hh   = (const float*)d_in[9];
    const float* dec_W  = (const float*)d_in[10];
    const float* dec_b  = (const float*)d_in[11];
    float* out = (float*)d_out;

    float *sg, *bias2, *zero_bias;
    cudaGetSymbolAddress((void**)&sg,    g_sg);
    cudaGetSymbolAddress((void**)&bias2, g_bias2);
    cudaGetSymbolAddress((void**)&zero_bias, g_zero_bias);

    void *gh_f, *gc2_f, *obs_f, *e_f, *hh_f, *h1_f, *S_f, *ew_f, *fw_f, *wih_f, *whh_f, *wc2_f;
    cudaGetSymbolAddress(&gh_f,  g_gh_f);
    cudaGetSymbolAddress(&gc2_f, g_gc2_f);
    cudaGetSymbolAddress(&obs_f, g_obs_f);
    cudaGetSymbolAddress(&e_f,   g_e_f);
    cudaGetSymbolAddress(&hh_f,  g_hh_f);
    cudaGetSymbolAddress(&h1_f,  g_h1_f);
    cudaGetSymbolAddress(&S_f,   g_S_f);
    cudaGetSymbolAddress(&ew_f,  g_ew_f);
    cudaGetSymbolAddress(&fw_f,  g_fw_f);
    cudaGetSymbolAddress(&wih_f, g_wih_f);
    cudaGetSymbolAddress(&whh_f, g_whh_f);
    cudaGetSymbolAddress(&wc2_f, g_wc2_f);

    cudaFuncSetAttribute(mma_gemmh<true , false, true >, cudaFuncAttributeMaxDynamicSharedMemorySize, SM_TOTAL);
    cudaFuncSetAttribute(mma_gemmh<false, false, true >, cudaFuncAttributeMaxDynamicSharedMemorySize, SM_TOTAL);
    cudaFuncSetAttribute(mma_gemmh<false, true , false>, cudaFuncAttributeMaxDynamicSharedMemorySize, SM_TOTAL);

    typedef const __half* hfp;
    typedef __half* hfpm;

    convert_h<<<(NROWS * DIN / 4 + 255) / 256, 256>>>((const float4*)obs, (uint2*)obs_f, NROWS * DIN / 4);
    convert_weights<<<(188416 + 255) / 256, 256>>>(
        (const float4*)enc_W, (const float4*)fobs_W,
        (const float4*)W_ih, (const float4*)W_hh,
        (uint2*)ew_f, (uint2*)fw_f, (uint2*)wih_f, (uint2*)whh_f, (uint2*)wc2_f);
    bias2_kernel<<<(H4 + 255) / 256, 256>>>(b_ih, b_hh, bias2);

    const dim3 blk(256);
    const int rowBlocks = NROWS / 128;  // 512

    // 1) e = relu(obs @ enc_W^T + enc_b) -> fp16           M=256 (1 col blk)
    mma_gemmh<true, false, true><<<dim3(1, rowBlocks), blk, SM_TOTAL>>>(
        (hfp)obs_f, (hfp)ew_f, enc_b, nullptr, (hfpm)e_f, DIN, HD);
    // 2) h = e @ fobs_W^T + fobs_b -> fp16                 M=256
    mma_gemmh<false, false, true><<<dim3(1, rowBlocks), blk, SM_TOTAL>>>(
        (hfp)e_f, (hfp)fw_f, fobs_b, nullptr, (hfpm)hh_f, HD, HD);
    // 3) gh = h @ W_hh^T + b_hh -> fp16                    M=768 (3 col blks)
    mma_gemmh<false, false, true><<<dim3(3, rowBlocks), blk, SM_TOTAL>>>(
        (hfp)hh_f, (hfp)whh_f, b_hh, nullptr, (hfpm)gh_f, HD, H3);
    // 4) gates k=0 + agent sum -> h1 fp16, S fp16
    gates0S_kernel<<<NB, HD>>>((hfp)gh_f, b_ih, (hfp)hh_f, (hfpm)h1_f, (hfpm)S_f);
    // 5) Sg = S @ W_ih^T (zero bias) -> fp32               M=768
    mma_gemmh<false, true, false><<<dim3(3, NB / 128), blk, SM_TOTAL>>>(
        (hfp)S_f, (hfp)wih_f, zero_bias, sg, nullptr, HD, H3);
    // 6) gc2 = h1 @ Wc2^T + bias2 -> fp16                  M=1024 (4 col blks)
    mma_gemmh<false, false, true><<<dim3(4, rowBlocks), blk, SM_TOTAL>>>(
        (hfp)h1_f, (hfp)wc2_f, bias2, nullptr, (hfpm)gc2_f, HD, H4);
    // 7) gates k=1 + decoder -> out
    gates1_dec_kernel<<<NROWS / 4, 256>>>((hfp)gc2_f, sg, b_ih, (hfp)h1_f, dec_W, dec_b, out);
}

// round 15
// speedup vs baseline: 1.0264x; 1.0264x over previous
#include <cuda_runtime.h>
#include <cuda_fp16.h>
#include <math.h>
#include <stdint.h>

// Problem constants (B=2048, A=32, D=128, H=256)
#define NB    2048
#define NA    32
#define NROWS (NB * NA)   // 65536
#define DIN   128
#define HD    256
#define H3    768
#define H4    1024

// ---------------------------------------------------------------------------
// Scratch
// ---------------------------------------------------------------------------
__device__ float g_sg [(size_t)NB * H3];
__device__ float g_bias2[H4];
__device__ float g_bias23[H4];
__device__ float g_zero_bias[H3];   // never written -> stays zero

__device__ uint4 g_hgh_f [(size_t)NROWS * H4 / 8];   // [h (256) | gh (768)] per row
__device__ uint4 g_gc2_f [(size_t)NROWS * H4 / 8];   // [rz-combined 512 | Gih_n 256 | h_n 256]
__device__ uint4 g_obs_f [(size_t)NROWS * DIN / 8];
__device__ uint4 g_e_f   [(size_t)NROWS * HD / 8];
__device__ uint4 g_h1_f  [(size_t)NROWS * HD / 8];
__device__ uint4 g_S_f   [(size_t)NB * HD / 8];
__device__ uint4 g_ew_f  [(size_t)HD * DIN / 8];
__device__ uint4 g_fwT_f [(size_t)HD * HD / 8];      // fobs_W transposed (fp16)
__device__ uint4 g_w23_f [(size_t)H4 * HD / 8];      // [fobs_W (256) ; Wcomb (768)]
__device__ uint4 g_wih_f [(size_t)H3 * HD / 8];
__device__ uint4 g_whh_f [(size_t)H3 * HD / 8];
__device__ uint4 g_wc2_f [(size_t)H4 * HD / 8];      // combined weight for gc2

__device__ __forceinline__ float sigmoidf_(float x) { return 1.0f / (1.0f + expf(-x)); }

__device__ __forceinline__ uint32_t smem_to_u32(const void* p) {
    uint32_t a;
    asm("{ .reg .u64 t; cvta.to.shared.u64 t, %1; cvt.u32.u64 %0, t; }" : "=r"(a) : "l"(p));
    return a;
}

#define SMEM_SWIZZLE_128B(off) ((off) ^ (((off) >> 3) & 0x70))

// ---------------------------------------------------------------------------
// primitives
// ---------------------------------------------------------------------------
__device__ __forceinline__ void mma_f16(float* c, uint32_t a0, uint32_t a1, uint32_t a2,
                                        uint32_t a3, uint32_t b0, uint32_t b1) {
    asm volatile(
        "mma.sync.aligned.m16n8k16.row.col.f32.f16.f16.f32 "
        "{%0,%1,%2,%3}, {%4,%5,%6,%7}, {%8,%9}, {%0,%1,%2,%3};"
        : "+f"(c[0]), "+f"(c[1]), "+f"(c[2]), "+f"(c[3])
        : "r"(a0), "r"(a1), "r"(a2), "r"(a3), "r"(b0), "r"(b1));
}
__device__ __forceinline__ void ldm_x4(uint32_t* r, uint32_t addr) {
    asm volatile("ldmatrix.sync.aligned.m8n8.x4.shared.b16 {%0,%1,%2,%3}, [%4];"
                 : "=r"(r[0]), "=r"(r[1]), "=r"(r[2]), "=r"(r[3]) : "r"(addr));
}
__device__ __forceinline__ void ldm_x2(uint32_t* r, uint32_t addr) {
    asm volatile("ldmatrix.sync.aligned.m8n8.x2.shared.b16 {%0,%1}, [%2];"
                 : "=r"(r[0]), "=r"(r[1]) : "r"(addr));
}
__device__ __forceinline__ void cp16(uint32_t dst, const void* src) {
    asm volatile("cp.async.cg.shared.global [%0], [%1], 16;" :: "r"(dst), "l"(src));
}
#define CP_COMMIT()  asm volatile("cp.async.commit_group;")
#define CP_WAIT(n)   asm volatile("cp.async.wait_group %0;" :: "n"(n))

__device__ __forceinline__ uint32_t pack_h2(float a, float b) {
    __half2 h = __floats2half2_rn(a, b);
    return *reinterpret_cast<uint32_t*>(&h);
}
__device__ __forceinline__ float4 h4_to_f4(uint2 u) {
    float2 fa = __half22float2(*reinterpret_cast<__half2*>(&u.x));
    float2 fb = __half22float2(*reinterpret_cast<__half2*>(&u.y));
    return make_float4(fa.x, fa.y, fb.x, fb.y);
}

// ---------------------------------------------------------------------------
// conversions
// ---------------------------------------------------------------------------
__global__ void convert_h(const float4* __restrict__ src, uint2* __restrict__ dst, int n4)
{
    const int i = blockIdx.x * blockDim.x + threadIdx.x;
    if (i >= n4) return;
    float4 v = src[i];
    uint2 o;
    o.x = pack_h2(v.x, v.y);
    o.y = pack_h2(v.z, v.w);
    dst[i] = o;
}

// Weight conversions in one launch (float4 units):
//  [0,8192)        ew -> ew_f
//  [8192,24576)    fobs_W -> w23_f rows 0..255
//  [24576,73728)   wih -> wih_f
//  [73728,122880)  whh -> whh_f
//  [122880,155648) combined rz: whh[i] - wih[i]/32 -> wc2_f[0:32768)
//  [155648,172032) wih rows 512..767 -> wc2_f[32768:49152)
//  [172032,188416) whh rows 512..767 -> wc2_f[49152:65536)
__global__ void convert_weights(const float4* __restrict__ ew, const float4* __restrict__ fw,
                                const float4* __restrict__ wih, const float4* __restrict__ whh,
                                uint2* __restrict__ ew_f, uint2* __restrict__ w23_f,
                                uint2* __restrict__ wih_f, uint2* __restrict__ whh_f,
                                uint2* __restrict__ wc2_f)
{
    const int gid = blockIdx.x * blockDim.x + threadIdx.x;
    float4 v;
    uint2* dst;
    int i;
    if (gid < 8192)        { i = gid;          v = ew[i];  dst = ew_f + i; }
    else if (gid < 24576)  { i = gid - 8192;   v = fw[i];  dst = w23_f + i; }
    else if (gid < 73728)  { i = gid - 24576;  v = wih[i]; dst = wih_f + i; }
    else if (gid < 122880) { i = gid - 73728;  v = whh[i]; dst = whh_f + i; }
    else if (gid < 155648) {
        i = gid - 122880;
        float4 a = whh[i], b = wih[i];
        v.x = a.x - b.x * 0.03125f;  v.y = a.y - b.y * 0.03125f;
        v.z = a.z - b.z * 0.03125f;  v.w = a.w - b.w * 0.03125f;
        dst = wc2_f + i;
    }
    else if (gid < 172032) { i = gid - 155648; v = wih[32768 + i]; dst = wc2_f + 32768 + i; }
    else if (gid < 188416) { i = gid - 172032; v = whh[32768 + i]; dst = wc2_f + 49152 + i; }
    else return;
    uint2 o;
    o.x = pack_h2(v.x, v.y);
    o.y = pack_h2(v.z, v.w);
    *dst = o;
}

// fobs_W transpose -> fp16 (writes coalesced): fwT[m*256+j] = fw[j*256+m]
__global__ void transpose_fw(const float* __restrict__ fw, __half* __restrict__ fwT)
{
    const int idx = blockIdx.x * blockDim.x + threadIdx.x;  // over 65536
    const int m = idx >> 8, j = idx & 255;
    fwT[idx] = __float2half_rn(fw[j * HD + m]);
}

// bias2[1024]: [b_ih+b_hh (512) | 0 (256) | b_hh[512..768) (256)]
// bias23[1024]: [fobs_b (256) | W_hh@fobs_b + b_hh (768)]
__global__ void biases_kernel(const float* __restrict__ b_ih, const float* __restrict__ b_hh,
                              const float* __restrict__ fobs_b, const float* __restrict__ W_hh,
                              float* __restrict__ bias2, float* __restrict__ bias23)
{
    const int i = blockIdx.x * blockDim.x + threadIdx.x;
    if (i >= H4) return;
    // bias2
    float v;
    if (i < 512)      v = b_ih[i] + b_hh[i];
    else if (i < 768) v = 0.f;
    else              v = b_hh[i - 256];
    bias2[i] = v;
    // bias23
    float w;
    if (i < 256) {
        w = fobs_b[i];
    } else {
        const int r = i - 256;
        float s = 0.f;
        const float* row = W_hh + (size_t)r * HD;
        for (int j = 0; j < HD; j++) s += row[j] * fobs_b[j];
        w = s + b_hh[r];
    }
    bias23[i] = w;
}

// ---------------------------------------------------------------------------
// fp16 GEMM (R13 config): cp.async 3-stage, 1 sync/chunk, fragment dbuf.
// CTA tile 128x128, KC=64, 8 warps (2m x 4n, warp 64x32), 2 CTAs/SM.
// ---------------------------------------------------------------------------
#define ST_AH 0
#define ST_WH 16384
#define ST_SZ 32768
#define SM_TOTAL (3 * ST_SZ)

template <bool RELU, bool WF32, bool WHALF>
__global__ __launch_bounds__(256, 2)
void mma_gemmh(const __half* __restrict__ Ag, const __half* __restrict__ Wg,
               const float* __restrict__ bias, float* __restrict__ C,
               __half* __restrict__ Ch, int K, int M)
{
    extern __shared__ char smem[];
    const uint32_t sb = smem_to_u32(smem);
    const int tid  = threadIdx.x;
    const int wid  = tid >> 5;
    const int lane = tid & 31;
    const int row0 = blockIdx.y * 128;
    const int col0 = blockIdx.x * 128;
    const int wm0  = (wid >> 2) * 64;
    const int wn0  = (wid & 3) * 32;

    const int a_row = wm0 + (lane & 15);
    const int a_kb  = ((lane >> 4) & 1) * 16;
    const int b_row = wn0 + (lane & 7);
    const int b_kb  = ((lane >> 3) & 1) * 16;

    const int r0_ = tid >> 3, k00 = (tid & 7) * 8;
    const uint32_t sw0 = SMEM_SWIZZLE_128B((uint32_t)(r0_ * 128 + k00 * 2));
    const __half* pA0 = Ag + (size_t)(row0 + r0_) * K + k00;
    const __half* pW0 = Wg + (size_t)(col0 + r0_) * K + k00;
    const size_t itK = (size_t)32 * K;

    float acc[4][4][4];
#pragma unroll
    for (int i = 0; i < 4; i++)
#pragma unroll
        for (int j = 0; j < 4; j++)
#pragma unroll
            for (int q = 0; q < 4; q++) acc[i][j][q] = 0.f;

    const int nch = K >> 6;

#pragma unroll
    for (int it = 0; it < 4; it++) {
        cp16(sb + ST_AH + sw0 + it * 4096, pA0 + it * itK);
        cp16(sb + ST_WH + sw0 + it * 4096, pW0 + it * itK);
    }
    CP_COMMIT();
    if (nch > 1) {
#pragma unroll
        for (int it = 0; it < 4; it++) {
            cp16(sb + ST_SZ + ST_AH + sw0 + it * 4096, pA0 + it * itK + 64);
            cp16(sb + ST_SZ + ST_WH + sw0 + it * 4096, pW0 + it * itK + 64);
        }
    }
    CP_COMMIT();

    uint32_t Af[2][4][4], Bf[2][4][2];

    for (int ch = 0; ch < nch; ch++) {
        const uint32_t sbase = sb + (uint32_t)(ch % 3) * ST_SZ;
        if (ch + 1 < nch) { CP_WAIT(1); } else { CP_WAIT(0); }
        __syncthreads();
        if (ch + 2 < nch) {
            const uint32_t nbase = sb + (uint32_t)((ch + 2) % 3) * ST_SZ;
            const int koff = (ch + 2) * 64;
#pragma unroll
            for (int it = 0; it < 4; it++) {
                cp16(nbase + ST_AH + sw0 + it * 4096, pA0 + it * itK + koff);
                cp16(nbase + ST_WH + sw0 + it * 4096, pW0 + it * itK + koff);
            }
            CP_COMMIT();
        } else {
            CP_COMMIT();
        }

        // preload fragments for ks=0
#pragma unroll
        for (int fm = 0; fm < 4; fm++) {
            uint32_t loc = SMEM_SWIZZLE_128B((uint32_t)((a_row + fm * 16) * 128 + a_kb));
            ldm_x4(Af[0][fm], sbase + ST_AH + loc);
        }
#pragma unroll
        for (int fn = 0; fn < 4; fn++) {
            uint32_t loc = SMEM_SWIZZLE_128B((uint32_t)((b_row + fn * 8) * 128 + b_kb));
            ldm_x2(Bf[0][fn], sbase + ST_WH + loc);
        }

#pragma unroll
        for (int ks = 0; ks < 4; ks++) {
            const int cur = ks & 1, nxt = cur ^ 1;
            if (ks < 3) {
#pragma unroll
                for (int fm = 0; fm < 4; fm++) {
                    uint32_t loc = SMEM_SWIZZLE_128B(
                        (uint32_t)((a_row + fm * 16) * 128 + (ks + 1) * 32 + a_kb));
                    ldm_x4(Af[nxt][fm], sbase + ST_AH + loc);
                }
#pragma unroll
                for (int fn = 0; fn < 4; fn++) {
                    uint32_t loc = SMEM_SWIZZLE_128B(
                        (uint32_t)((b_row + fn * 8) * 128 + (ks + 1) * 32 + b_kb));
                    ldm_x2(Bf[nxt][fn], sbase + ST_WH + loc);
                }
            }
#pragma unroll
            for (int fm = 0; fm < 4; fm++)
#pragma unroll
                for (int fn = 0; fn < 4; fn++)
                    mma_f16(acc[fm][fn], Af[cur][fm][0], Af[cur][fm][1], Af[cur][fm][2],
                            Af[cur][fm][3], Bf[cur][fn][0], Bf[cur][fn][1]);
        }
    }

    const int gid  = lane >> 2;
    const int tid4 = lane & 3;
#pragma unroll
    for (int fn = 0; fn < 4; fn++) {
        const int col = col0 + wn0 + fn * 8 + 2 * tid4;
        const float b0 = bias[col], b1 = bias[col + 1];
#pragma unroll
        for (int fm = 0; fm < 4; fm++) {
            const int rlo = row0 + wm0 + fm * 16 + gid;
            float2 v0, v1;
            v0.x = acc[fm][fn][0] + b0;  v0.y = acc[fm][fn][1] + b1;
            v1.x = acc[fm][fn][2] + b0;  v1.y = acc[fm][fn][3] + b1;
            if (RELU) {
                v0.x = fmaxf(v0.x, 0.f); v0.y = fmaxf(v0.y, 0.f);
                v1.x = fmaxf(v1.x, 0.f); v1.y = fmaxf(v1.y, 0.f);
            }
            if (WF32) {
                *reinterpret_cast<float2*>(C + (size_t)rlo * M + col)       = v0;
                *reinterpret_cast<float2*>(C + (size_t)(rlo + 8) * M + col) = v1;
            }
            if (WHALF) {
                *reinterpret_cast<uint32_t*>(Ch + (size_t)rlo * M + col)       = pack_h2(v0.x, v0.y);
                *reinterpret_cast<uint32_t*>(Ch + (size_t)(rlo + 8) * M + col) = pack_h2(v1.x, v1.y);
            }
        }
    }
}

// ---------------------------------------------------------------------------
// GRU gates k=0 + per-batch agent sum.
// hgh row layout (fp16, 1024): [h (256) | gh_r (256) | gh_z (256) | gh_n (256)]
// ---------------------------------------------------------------------------
__global__ void gates0S_kernel(const __half* __restrict__ hgh,
                               const float* __restrict__ b_ih,
                               __half* __restrict__ h1_f,
                               __half* __restrict__ S_f)
{
    const int b = blockIdx.x;
    const int j = threadIdx.x;
    const __half* base = hgh + (size_t)b * NA * H4;
    __half* h1fb       = h1_f + (size_t)b * NA * HD;
    const float bir = b_ih[j], biz = b_ih[HD + j], bin = b_ih[2 * HD + j];
    float s = 0.f;
    for (int a = 0; a < NA; a++) {
        const __half* row = base + a * H4;
        float hh = __half2float(row[j]);
        float gr = __half2float(row[256 + j]);
        float gz = __half2float(row[512 + j]);
        float gn = __half2float(row[768 + j]);
        float r = sigmoidf_(bir + gr), z = sigmoidf_(biz + gz);
        float n = tanhf(bin + r * gn);
        float o = (1.f - z) * n + z * hh;
        h1fb[a * HD + j] = __float2half_rn(o);
        s += o;
    }
    S_f[(size_t)b * HD + j] = __float2half_rn(s);
}

// ---------------------------------------------------------------------------
// GRU gates k=1 + decoder, combined-rz formulation.
// gc2 row layout (fp16, 1024): [rz (512) | Gih_n (256) | h_n (256, incl b_hh_n)]
// ---------------------------------------------------------------------------
__global__ void gates1_dec_kernel(const __half* __restrict__ gc2,
                                  const float* __restrict__ Sg,
                                  const float* __restrict__ b_ih,
                                  const __half* __restrict__ h1_f,
                                  const float* __restrict__ dec_W,
                                  const float* __restrict__ dec_b,
                                  float* __restrict__ out)
{
    const int tid = threadIdx.x;
    const int i = blockIdx.x * 4 + (tid >> 6);
    const int b = i >> 5;
    const int q = tid & 63;
    const uint2*  gc = reinterpret_cast<const uint2*>(gc2 + (size_t)i * H4);
    const float4* sg = reinterpret_cast<const float4*>(Sg + (size_t)b * H3);
    const float4* bi = reinterpret_cast<const float4*>(b_ih);
    const float inv = 1.f / (float)NA;

    float4 rzr  = h4_to_f4(gc[q]);
    float4 rzz  = h4_to_f4(gc[64 + q]);
    float4 gihn = h4_to_f4(gc[128 + q]);
    float4 hn   = h4_to_f4(gc[192 + q]);
    float4 sg_r = sg[q], sg_z = sg[64 + q], sg_n = sg[128 + q];
    float4 bi_n = bi[128 + q];

    float4 hp = h4_to_f4(reinterpret_cast<const uint2*>(h1_f)[(size_t)i * 64 + q]);
    float4 dw = reinterpret_cast<const float4*>(dec_W)[q];

    float p = 0.f;
    { float r = sigmoidf_(rzr.x + sg_r.x * inv), z = sigmoidf_(rzz.x + sg_z.x * inv);
      float n = tanhf((sg_n.x - gihn.x) * inv + bi_n.x + r * hn.x);
      p += ((1.f - z) * n + z * hp.x) * dw.x; }
    { float r = sigmoidf_(rzr.y + sg_r.y * inv), z = sigmoidf_(rzz.y + sg_z.y * inv);
      float n = tanhf((sg_n.y - gihn.y) * inv + bi_n.y + r * hn.y);
      p += ((1.f - z) * n + z * hp.y) * dw.y; }
    { float r = sigmoidf_(rzr.z + sg_r.z * inv), z = sigmoidf_(rzz.z + sg_z.z * inv);
      float n = tanhf((sg_n.z - gihn.z) * inv + bi_n.z + r * hn.z);
      p += ((1.f - z) * n + z * hp.z) * dw.z; }
    { float r = sigmoidf_(rzr.w + sg_r.w * inv), z = sigmoidf_(rzz.w + sg_z.w * inv);
      float n = tanhf((sg_n.w - gihn.w) * inv + bi_n.w + r * hn.w);
      p += ((1.f - z) * n + z * hp.w) * dw.w; }
#pragma unroll
    for (int o = 16; o > 0; o >>= 1) p += __shfl_down_sync(0xffffffffu, p, o);
    __shared__ float red[8];
    if ((tid & 31) == 0) red[tid >> 5] = p;
    __syncthreads();
    if (tid < 4) out[blockIdx.x * 4 + tid] = red[2 * tid] + red[2 * tid + 1] + dec_b[0];
}

// ---------------------------------------------------------------------------
// Launch
// ---------------------------------------------------------------------------
extern "C" void kernel_launch(void* const* d_in, const int* in_sizes, int n_in,
                              void* d_out, int out_size)
{
    const float* obs    = (const float*)d_in[0];
    const float* enc_W  = (const float*)d_in[2];
    const float* enc_b  = (const float*)d_in[3];
    const float* fobs_W = (const float*)d_in[4];
    const float* fobs_b = (const float*)d_in[5];
    const float* W_ih   = (const float*)d_in[6];
    const float* b_ih   = (const float*)d_in[7];
    const float* W_hh   = (const float*)d_in[8];
    const float* b_hh   = (const float*)d_in[9];
    const float* dec_W  = (const float*)d_in[10];
    const float* dec_b  = (const float*)d_in[11];
    float* out = (float*)d_out;

    float *sg, *bias2, *bias23, *zero_bias;
    cudaGetSymbolAddress((void**)&sg,     g_sg);
    cudaGetSymbolAddress((void**)&bias2,  g_bias2);
    cudaGetSymbolAddress((void**)&bias23, g_bias23);
    cudaGetSymbolAddress((void**)&zero_bias, g_zero_bias);

    void *hgh_f, *gc2_f, *obs_f, *e_f, *h1_f, *S_f, *ew_f, *fwT_f, *w23_f, *wih_f, *whh_f, *wc2_f;
    cudaGetSymbolAddress(&hgh_f, g_hgh_f);
    cudaGetSymbolAddress(&gc2_f, g_gc2_f);
    cudaGetSymbolAddress(&obs_f, g_obs_f);
    cudaGetSymbolAddress(&e_f,   g_e_f);
    cudaGetSymbolAddress(&h1_f,  g_h1_f);
    cudaGetSymbolAddress(&S_f,   g_S_f);
    cudaGetSymbolAddress(&ew_f,  g_ew_f);
    cudaGetSymbolAddress(&fwT_f, g_fwT_f);
    cudaGetSymbolAddress(&w23_f, g_w23_f);
    cudaGetSymbolAddress(&wih_f, g_wih_f);
    cudaGetSymbolAddress(&whh_f, g_whh_f);
    cudaGetSymbolAddress(&wc2_f, g_wc2_f);

    cudaFuncSetAttribute(mma_gemmh<true , false, true >, cudaFuncAttributeMaxDynamicSharedMemorySize, SM_TOTAL);
    cudaFuncSetAttribute(mma_gemmh<false, false, true >, cudaFuncAttributeMaxDynamicSharedMemorySize, SM_TOTAL);
    cudaFuncSetAttribute(mma_gemmh<false, true , false>, cudaFuncAttributeMaxDynamicSharedMemorySize, SM_TOTAL);

    typedef const __half* hfp;
    typedef __half* hfpm;

    convert_h<<<(NROWS * DIN / 4 + 255) / 256, 256>>>((const float4*)obs, (uint2*)obs_f, NROWS * DIN / 4);
    convert_weights<<<(188416 + 255) / 256, 256>>>(
        (const float4*)enc_W, (const float4*)fobs_W,
        (const float4*)W_ih, (const float4*)W_hh,
        (uint2*)ew_f, (uint2*)w23_f, (uint2*)wih_f, (uint2*)whh_f, (uint2*)wc2_f);
    transpose_fw<<<(HD * HD + 255) / 256, 256>>>(fobs_W, (hfpm)fwT_f);
    biases_kernel<<<(H4 + 255) / 256, 256>>>(b_ih, b_hh, fobs_b, W_hh, bias2, bias23);

    const dim3 blk(256);
    const int rowBlocks = NROWS / 128;  // 512

    // 0) Wcomb = W_hh @ fobs_W  -> w23_f rows 256..1023   (768x256, K=256)
    mma_gemmh<false, false, true><<<dim3(2, H3 / 128), blk, SM_TOTAL>>>(
        (hfp)whh_f, (hfp)fwT_f, zero_bias, nullptr,
        (hfpm)w23_f + (size_t)HD * HD, HD, HD);
    // 1) e = relu(obs @ enc_W^T + enc_b) -> fp16
    mma_gemmh<true, false, true><<<dim3(2, rowBlocks), blk, SM_TOTAL>>>(
        (hfp)obs_f, (hfp)ew_f, enc_b, nullptr, (hfpm)e_f, DIN, HD);
    // 2+3) [h | gh] = e @ [fobs_W; Wcomb]^T + bias23 -> fp16  (M=1024)
    mma_gemmh<false, false, true><<<dim3(8, rowBlocks), blk, SM_TOTAL>>>(
        (hfp)e_f, (hfp)w23_f, bias23, nullptr, (hfpm)hgh_f, HD, H4);
    // 4) gates k=0 + agent sum -> h1 fp16, S fp16
    gates0S_kernel<<<NB, HD>>>((hfp)hgh_f, b_ih, (hfpm)h1_f, (hfpm)S_f);
    // 5) Sg = S @ W_ih^T (zero bias) -> fp32
    mma_gemmh<false, true, false><<<dim3(6, NB / 128), blk, SM_TOTAL>>>(
        (hfp)S_f, (hfp)wih_f, zero_bias, sg, nullptr, HD, H3);
    // 6) gc2 = h1 @ Wc2^T + bias2 -> fp16   (M=1024)
    mma_gemmh<false, false, true><<<dim3(8, rowBlocks), blk, SM_TOTAL>>>(
        (hfp)h1_f, (hfp)wc2_f, bias2, nullptr, (hfpm)gc2_f, HD, H4);
    // 7) gates k=1 + decoder -> out
    gates1_dec_kernel<<<NROWS / 4, 256>>>((hfp)gc2_f, sg, b_ih, (hfp)h1_f, dec_W, dec_b, out);
}

// round 16
// speedup vs baseline: 1.1189x; 1.0901x over previous
#include <cuda_runtime.h>
#include <cuda_fp16.h>
#include <math.h>
#include <stdint.h>

// Problem constants (B=2048, A=32, D=128, H=256)
#define NB    2048
#define NA    32
#define NROWS (NB * NA)   // 65536
#define DIN   128
#define HD    256
#define H3    768
#define H4    1024

// ---------------------------------------------------------------------------
// Scratch
// ---------------------------------------------------------------------------
__device__ float g_sg [(size_t)NB * H3];
__device__ float g_bias2[H4];
__device__ float g_bias23[H4];
__device__ float g_zero_bias[H3];   // never written -> stays zero

__device__ uint4 g_hgh_f [(size_t)NROWS * H4 / 8];   // [h (256) | gh (768)] per row
__device__ uint4 g_gc2_f [(size_t)NROWS * H4 / 8];   // [rz-combined 512 | Gih_n 256 | h_n 256]
__device__ uint4 g_obs_f [(size_t)NROWS * DIN / 8];
__device__ uint4 g_e_f   [(size_t)NROWS * HD / 8];
__device__ uint4 g_h1_f  [(size_t)NROWS * HD / 8];
__device__ uint4 g_S_f   [(size_t)NB * HD / 8];
__device__ uint4 g_ew_f  [(size_t)HD * DIN / 8];
__device__ uint4 g_fwT_f [(size_t)HD * HD / 8];      // fobs_W transposed (fp16)
__device__ uint4 g_w23_f [(size_t)H4 * HD / 8];      // [fobs_W (256) ; Wcomb (768)]
__device__ uint4 g_wih_f [(size_t)H3 * HD / 8];
__device__ uint4 g_whh_f [(size_t)H3 * HD / 8];
__device__ uint4 g_wc2_f [(size_t)H4 * HD / 8];      // combined weight for gc2

__device__ __forceinline__ float sigmoidf_(float x) { return 1.0f / (1.0f + expf(-x)); }

__device__ __forceinline__ uint32_t smem_to_u32(const void* p) {
    uint32_t a;
    asm("{ .reg .u64 t; cvta.to.shared.u64 t, %1; cvt.u32.u64 %0, t; }" : "=r"(a) : "l"(p));
    return a;
}

#define SMEM_SWIZZLE_128B(off) ((off) ^ (((off) >> 3) & 0x70))

// ---------------------------------------------------------------------------
// primitives
// ---------------------------------------------------------------------------
__device__ __forceinline__ void mma_f16(float* c, uint32_t a0, uint32_t a1, uint32_t a2,
                                        uint32_t a3, uint32_t b0, uint32_t b1) {
    asm volatile(
        "mma.sync.aligned.m16n8k16.row.col.f32.f16.f16.f32 "
        "{%0,%1,%2,%3}, {%4,%5,%6,%7}, {%8,%9}, {%0,%1,%2,%3};"
        : "+f"(c[0]), "+f"(c[1]), "+f"(c[2]), "+f"(c[3])
        : "r"(a0), "r"(a1), "r"(a2), "r"(a3), "r"(b0), "r"(b1));
}
__device__ __forceinline__ void ldm_x4(uint32_t* r, uint32_t addr) {
    asm volatile("ldmatrix.sync.aligned.m8n8.x4.shared.b16 {%0,%1,%2,%3}, [%4];"
                 : "=r"(r[0]), "=r"(r[1]), "=r"(r[2]), "=r"(r[3]) : "r"(addr));
}
__device__ __forceinline__ void ldm_x2(uint32_t* r, uint32_t addr) {
    asm volatile("ldmatrix.sync.aligned.m8n8.x2.shared.b16 {%0,%1}, [%2];"
                 : "=r"(r[0]), "=r"(r[1]) : "r"(addr));
}
__device__ __forceinline__ void cp16(uint32_t dst, const void* src) {
    asm volatile("cp.async.cg.shared.global [%0], [%1], 16;" :: "r"(dst), "l"(src));
}
#define CP_COMMIT()  asm volatile("cp.async.commit_group;")
#define CP_WAIT(n)   asm volatile("cp.async.wait_group %0;" :: "n"(n))

__device__ __forceinline__ uint32_t pack_h2(float a, float b) {
    __half2 h = __floats2half2_rn(a, b);
    return *reinterpret_cast<uint32_t*>(&h);
}
__device__ __forceinline__ float4 h4_to_f4(uint2 u) {
    float2 fa = __half22float2(*reinterpret_cast<__half2*>(&u.x));
    float2 fb = __half22float2(*reinterpret_cast<__half2*>(&u.y));
    return make_float4(fa.x, fa.y, fb.x, fb.y);
}

// ---------------------------------------------------------------------------
// conversions
// ---------------------------------------------------------------------------
__global__ void convert_h(const float4* __restrict__ src, uint2* __restrict__ dst, int n4)
{
    const int i = blockIdx.x * blockDim.x + threadIdx.x;
    if (i >= n4) return;
    float4 v = src[i];
    uint2 o;
    o.x = pack_h2(v.x, v.y);
    o.y = pack_h2(v.z, v.w);
    dst[i] = o;
}

// Weight conversions in one launch (float4 units):
//  [0,8192)        ew -> ew_f
//  [8192,24576)    fobs_W -> w23_f rows 0..255
//  [24576,73728)   wih -> wih_f
//  [73728,122880)  whh -> whh_f
//  [122880,155648) combined rz: whh[i] - wih[i]/32 -> wc2_f[0:32768)
//  [155648,172032) wih rows 512..767 -> wc2_f[32768:49152)
//  [172032,188416) whh rows 512..767 -> wc2_f[49152:65536)
__global__ void convert_weights(const float4* __restrict__ ew, const float4* __restrict__ fw,
                                const float4* __restrict__ wih, const float4* __restrict__ whh,
                                uint2* __restrict__ ew_f, uint2* __restrict__ w23_f,
                                uint2* __restrict__ wih_f, uint2* __restrict__ whh_f,
                                uint2* __restrict__ wc2_f)
{
    const int gid = blockIdx.x * blockDim.x + threadIdx.x;
    float4 v;
    uint2* dst;
    int i;
    if (gid < 8192)        { i = gid;          v = ew[i];  dst = ew_f + i; }
    else if (gid < 24576)  { i = gid - 8192;   v = fw[i];  dst = w23_f + i; }
    else if (gid < 73728)  { i = gid - 24576;  v = wih[i]; dst = wih_f + i; }
    else if (gid < 122880) { i = gid - 73728;  v = whh[i]; dst = whh_f + i; }
    else if (gid < 155648) {
        i = gid - 122880;
        float4 a = whh[i], b = wih[i];
        v.x = a.x - b.x * 0.03125f;  v.y = a.y - b.y * 0.03125f;
        v.z = a.z - b.z * 0.03125f;  v.w = a.w - b.w * 0.03125f;
        dst = wc2_f + i;
    }
    else if (gid < 172032) { i = gid - 155648; v = wih[32768 + i]; dst = wc2_f + 32768 + i; }
    else if (gid < 188416) { i = gid - 172032; v = whh[32768 + i]; dst = wc2_f + 49152 + i; }
    else return;
    uint2 o;
    o.x = pack_h2(v.x, v.y);
    o.y = pack_h2(v.z, v.w);
    *dst = o;
}

// fobs_W transpose -> fp16 (writes coalesced): fwT[m*256+j] = fw[j*256+m]
__global__ void transpose_fw(const float* __restrict__ fw, __half* __restrict__ fwT)
{
    const int idx = blockIdx.x * blockDim.x + threadIdx.x;  // over 65536
    const int m = idx >> 8, j = idx & 255;
    fwT[idx] = __float2half_rn(fw[j * HD + m]);
}

// Parallel bias builder.
//  blocks 0..95   : Wcomb bias rows (one warp per row, warp reduction)
//                   bias23[256+r] = W_hh[r,:]@fobs_b + b_hh[r]
//  blocks 96..99  : bias2[1024] = [b_ih+b_hh | 0 | b_hh_n]; bias23[0:256) = fobs_b
__global__ void biases_kernel(const float* __restrict__ b_ih, const float* __restrict__ b_hh,
                              const float* __restrict__ fobs_b, const float* __restrict__ W_hh,
                              float* __restrict__ bias2, float* __restrict__ bias23)
{
    const int blk = blockIdx.x;
    if (blk < 96) {
        const int warp = threadIdx.x >> 5, lane = threadIdx.x & 31;
        const int r = blk * 8 + warp;          // 0..767
        const float* row = W_hh + (size_t)r * HD;
        float s = 0.f;
#pragma unroll
        for (int j = lane; j < HD; j += 32) s += row[j] * fobs_b[j];
#pragma unroll
        for (int o = 16; o > 0; o >>= 1) s += __shfl_down_sync(0xffffffffu, s, o);
        if (lane == 0) bias23[256 + r] = s + b_hh[r];
    } else {
        const int i = (blk - 96) * 256 + threadIdx.x;  // 0..1023
        if (i < H4) {
            float v;
            if (i < 512)      v = b_ih[i] + b_hh[i];
            else if (i < 768) v = 0.f;
            else              v = b_hh[i - 256];
            bias2[i] = v;
            if (i < 256) bias23[i] = fobs_b[i];
        }
    }
}

// ---------------------------------------------------------------------------
// fp16 GEMM (R13 config): cp.async 3-stage, 1 sync/chunk, fragment dbuf.
// CTA tile 128x128, KC=64, 8 warps (2m x 4n, warp 64x32), 2 CTAs/SM.
// ---------------------------------------------------------------------------
#define ST_AH 0
#define ST_WH 16384
#define ST_SZ 32768
#define SM_TOTAL (3 * ST_SZ)

template <bool RELU, bool WF32, bool WHALF>
__global__ __launch_bounds__(256, 2)
void mma_gemmh(const __half* __restrict__ Ag, const __half* __restrict__ Wg,
               const float* __restrict__ bias, float* __restrict__ C,
               __half* __restrict__ Ch, int K, int M)
{
    extern __shared__ char smem[];
    const uint32_t sb = smem_to_u32(smem);
    const int tid  = threadIdx.x;
    const int wid  = tid >> 5;
    const int lane = tid & 31;
    const int row0 = blockIdx.y * 128;
    const int col0 = blockIdx.x * 128;
    const int wm0  = (wid >> 2) * 64;
    const int wn0  = (wid & 3) * 32;

    const int a_row = wm0 + (lane & 15);
    const int a_kb  = ((lane >> 4) & 1) * 16;
    const int b_row = wn0 + (lane & 7);
    const int b_kb  = ((lane >> 3) & 1) * 16;

    const int r0_ = tid >> 3, k00 = (tid & 7) * 8;
    const uint32_t sw0 = SMEM_SWIZZLE_128B((uint32_t)(r0_ * 128 + k00 * 2));
    const __half* pA0 = Ag + (size_t)(row0 + r0_) * K + k00;
    const __half* pW0 = Wg + (size_t)(col0 + r0_) * K + k00;
    const size_t itK = (size_t)32 * K;

    float acc[4][4][4];
#pragma unroll
    for (int i = 0; i < 4; i++)
#pragma unroll
        for (int j = 0; j < 4; j++)
#pragma unroll
            for (int q = 0; q < 4; q++) acc[i][j][q] = 0.f;

    const int nch = K >> 6;

#pragma unroll
    for (int it = 0; it < 4; it++) {
        cp16(sb + ST_AH + sw0 + it * 4096, pA0 + it * itK);
        cp16(sb + ST_WH + sw0 + it * 4096, pW0 + it * itK);
    }
    CP_COMMIT();
    if (nch > 1) {
#pragma unroll
        for (int it = 0; it < 4; it++) {
            cp16(sb + ST_SZ + ST_AH + sw0 + it * 4096, pA0 + it * itK + 64);
            cp16(sb + ST_SZ + ST_WH + sw0 + it * 4096, pW0 + it * itK + 64);
        }
    }
    CP_COMMIT();

    uint32_t Af[2][4][4], Bf[2][4][2];

    for (int ch = 0; ch < nch; ch++) {
        const uint32_t sbase = sb + (uint32_t)(ch % 3) * ST_SZ;
        if (ch + 1 < nch) { CP_WAIT(1); } else { CP_WAIT(0); }
        __syncthreads();
        if (ch + 2 < nch) {
            const uint32_t nbase = sb + (uint32_t)((ch + 2) % 3) * ST_SZ;
            const int koff = (ch + 2) * 64;
#pragma unroll
            for (int it = 0; it < 4; it++) {
                cp16(nbase + ST_AH + sw0 + it * 4096, pA0 + it * itK + koff);
                cp16(nbase + ST_WH + sw0 + it * 4096, pW0 + it * itK + koff);
            }
            CP_COMMIT();
        } else {
            CP_COMMIT();
        }

        // preload fragments for ks=0
#pragma unroll
        for (int fm = 0; fm < 4; fm++) {
            uint32_t loc = SMEM_SWIZZLE_128B((uint32_t)((a_row + fm * 16) * 128 + a_kb));
            ldm_x4(Af[0][fm], sbase + ST_AH + loc);
        }
#pragma unroll
        for (int fn = 0; fn < 4; fn++) {
            uint32_t loc = SMEM_SWIZZLE_128B((uint32_t)((b_row + fn * 8) * 128 + b_kb));
            ldm_x2(Bf[0][fn], sbase + ST_WH + loc);
        }

#pragma unroll
        for (int ks = 0; ks < 4; ks++) {
            const int cur = ks & 1, nxt = cur ^ 1;
            if (ks < 3) {
#pragma unroll
                for (int fm = 0; fm < 4; fm++) {
                    uint32_t loc = SMEM_SWIZZLE_128B(
                        (uint32_t)((a_row + fm * 16) * 128 + (ks + 1) * 32 + a_kb));
                    ldm_x4(Af[nxt][fm], sbase + ST_AH + loc);
                }
#pragma unroll
                for (int fn = 0; fn < 4; fn++) {
                    uint32_t loc = SMEM_SWIZZLE_128B(
                        (uint32_t)((b_row + fn * 8) * 128 + (ks + 1) * 32 + b_kb));
                    ldm_x2(Bf[nxt][fn], sbase + ST_WH + loc);
                }
            }
#pragma unroll
            for (int fm = 0; fm < 4; fm++)
#pragma unroll
                for (int fn = 0; fn < 4; fn++)
                    mma_f16(acc[fm][fn], Af[cur][fm][0], Af[cur][fm][1], Af[cur][fm][2],
                            Af[cur][fm][3], Bf[cur][fn][0], Bf[cur][fn][1]);
        }
    }

    const int gid  = lane >> 2;
    const int tid4 = lane & 3;
#pragma unroll
    for (int fn = 0; fn < 4; fn++) {
        const int col = col0 + wn0 + fn * 8 + 2 * tid4;
        const float b0 = bias[col], b1 = bias[col + 1];
#pragma unroll
        for (int fm = 0; fm < 4; fm++) {
            const int rlo = row0 + wm0 + fm * 16 + gid;
            float2 v0, v1;
            v0.x = acc[fm][fn][0] + b0;  v0.y = acc[fm][fn][1] + b1;
            v1.x = acc[fm][fn][2] + b0;  v1.y = acc[fm][fn][3] + b1;
            if (RELU) {
                v0.x = fmaxf(v0.x, 0.f); v0.y = fmaxf(v0.y, 0.f);
                v1.x = fmaxf(v1.x, 0.f); v1.y = fmaxf(v1.y, 0.f);
            }
            if (WF32) {
                *reinterpret_cast<float2*>(C + (size_t)rlo * M + col)       = v0;
                *reinterpret_cast<float2*>(C + (size_t)(rlo + 8) * M + col) = v1;
            }
            if (WHALF) {
                *reinterpret_cast<uint32_t*>(Ch + (size_t)rlo * M + col)       = pack_h2(v0.x, v0.y);
                *reinterpret_cast<uint32_t*>(Ch + (size_t)(rlo + 8) * M + col) = pack_h2(v1.x, v1.y);
            }
        }
    }
}

// ---------------------------------------------------------------------------
// GRU gates k=0 + per-batch agent sum.
// hgh row layout (fp16, 1024): [h (256) | gh_r (256) | gh_z (256) | gh_n (256)]
// ---------------------------------------------------------------------------
__global__ void gates0S_kernel(const __half* __restrict__ hgh,
                               const float* __restrict__ b_ih,
                               __half* __restrict__ h1_f,
                               __half* __restrict__ S_f)
{
    const int b = blockIdx.x;
    const int j = threadIdx.x;
    const __half* base = hgh + (size_t)b * NA * H4;
    __half* h1fb       = h1_f + (size_t)b * NA * HD;
    const float bir = b_ih[j], biz = b_ih[HD + j], bin = b_ih[2 * HD + j];
    float s = 0.f;
    for (int a = 0; a < NA; a++) {
        const __half* row = base + a * H4;
        float hh = __half2float(row[j]);
        float gr = __half2float(row[256 + j]);
        float gz = __half2float(row[512 + j]);
        float gn = __half2float(row[768 + j]);
        float r = sigmoidf_(bir + gr), z = sigmoidf_(biz + gz);
        float n = tanhf(bin + r * gn);
        float o = (1.f - z) * n + z * hh;
        h1fb[a * HD + j] = __float2half_rn(o);
        s += o;
    }
    S_f[(size_t)b * HD + j] = __float2half_rn(s);
}

// ---------------------------------------------------------------------------
// GRU gates k=1 + decoder, combined-rz formulation.
// gc2 row layout (fp16, 1024): [rz (512) | Gih_n (256) | h_n (256, incl b_hh_n)]
// ---------------------------------------------------------------------------
__global__ void gates1_dec_kernel(const __half* __restrict__ gc2,
                                  const float* __restrict__ Sg,
                                  const float* __restrict__ b_ih,
                                  const __half* __restrict__ h1_f,
                                  const float* __restrict__ dec_W,
                                  const float* __restrict__ dec_b,
                                  float* __restrict__ out)
{
    const int tid = threadIdx.x;
    const int i = blockIdx.x * 4 + (tid >> 6);
    const int b = i >> 5;
    const int q = tid & 63;
    const uint2*  gc = reinterpret_cast<const uint2*>(gc2 + (size_t)i * H4);
    const float4* sg = reinterpret_cast<const float4*>(Sg + (size_t)b * H3);
    const float4* bi = reinterpret_cast<const float4*>(b_ih);
    const float inv = 1.f / (float)NA;

    float4 rzr  = h4_to_f4(gc[q]);
    float4 rzz  = h4_to_f4(gc[64 + q]);
    float4 gihn = h4_to_f4(gc[128 + q]);
    float4 hn   = h4_to_f4(gc[192 + q]);
    float4 sg_r = sg[q], sg_z = sg[64 + q], sg_n = sg[128 + q];
    float4 bi_n = bi[128 + q];

    float4 hp = h4_to_f4(reinterpret_cast<const uint2*>(h1_f)[(size_t)i * 64 + q]);
    float4 dw = reinterpret_cast<const float4*>(dec_W)[q];

    float p = 0.f;
    { float r = sigmoidf_(rzr.x + sg_r.x * inv), z = sigmoidf_(rzz.x + sg_z.x * inv);
      float n = tanhf((sg_n.x - gihn.x) * inv + bi_n.x + r * hn.x);
      p += ((1.f - z) * n + z * hp.x) * dw.x; }
    { float r = sigmoidf_(rzr.y + sg_r.y * inv), z = sigmoidf_(rzz.y + sg_z.y * inv);
      float n = tanhf((sg_n.y - gihn.y) * inv + bi_n.y + r * hn.y);
      p += ((1.f - z) * n + z * hp.y) * dw.y; }
    { float r = sigmoidf_(rzr.z + sg_r.z * inv), z = sigmoidf_(rzz.z + sg_z.z * inv);
      float n = tanhf((sg_n.z - gihn.z) * inv + bi_n.z + r * hn.z);
      p += ((1.f - z) * n + z * hp.z) * dw.z; }
    { float r = sigmoidf_(rzr.w + sg_r.w * inv), z = sigmoidf_(rzz.w + sg_z.w * inv);
      float n = tanhf((sg_n.w - gihn.w) * inv + bi_n.w + r * hn.w);
      p += ((1.f - z) * n + z * hp.w) * dw.w; }
#pragma unroll
    for (int o = 16; o > 0; o >>= 1) p += __shfl_down_sync(0xffffffffu, p, o);
    __shared__ float red[8];
    if ((tid & 31) == 0) red[tid >> 5] = p;
    __syncthreads();
    if (tid < 4) out[blockIdx.x * 4 + tid] = red[2 * tid] + red[2 * tid + 1] + dec_b[0];
}

// ---------------------------------------------------------------------------
// Launch
// ---------------------------------------------------------------------------
extern "C" void kernel_launch(void* const* d_in, const int* in_sizes, int n_in,
                              void* d_out, int out_size)
{
    const float* obs    = (const float*)d_in[0];
    const float* enc_W  = (const float*)d_in[2];
    const float* enc_b  = (const float*)d_in[3];
    const float* fobs_W = (const float*)d_in[4];
    const float* fobs_b = (const float*)d_in[5];
    const float* W_ih   = (const float*)d_in[6];
    const float* b_ih   = (const float*)d_in[7];
    const float* W_hh   = (const float*)d_in[8];
    const float* b_hh   = (const float*)d_in[9];
    const float* dec_W  = (const float*)d_in[10];
    const float* dec_b  = (const float*)d_in[11];
    float* out = (float*)d_out;

    float *sg, *bias2, *bias23, *zero_bias;
    cudaGetSymbolAddress((void**)&sg,     g_sg);
    cudaGetSymbolAddress((void**)&bias2,  g_bias2);
    cudaGetSymbolAddress((void**)&bias23, g_bias23);
    cudaGetSymbolAddress((void**)&zero_bias, g_zero_bias);

    void *hgh_f, *gc2_f, *obs_f, *e_f, *h1_f, *S_f, *ew_f, *fwT_f, *w23_f, *wih_f, *whh_f, *wc2_f;
    cudaGetSymbolAddress(&hgh_f, g_hgh_f);
    cudaGetSymbolAddress(&gc2_f, g_gc2_f);
    cudaGetSymbolAddress(&obs_f, g_obs_f);
    cudaGetSymbolAddress(&e_f,   g_e_f);
    cudaGetSymbolAddress(&h1_f,  g_h1_f);
    cudaGetSymbolAddress(&S_f,   g_S_f);
    cudaGetSymbolAddress(&ew_f,  g_ew_f);
    cudaGetSymbolAddress(&fwT_f, g_fwT_f);
    cudaGetSymbolAddress(&w23_f, g_w23_f);
    cudaGetSymbolAddress(&wih_f, g_wih_f);
    cudaGetSymbolAddress(&whh_f, g_whh_f);
    cudaGetSymbolAddress(&wc2_f, g_wc2_f);

    cudaFuncSetAttribute(mma_gemmh<true , false, true >, cudaFuncAttributeMaxDynamicSharedMemorySize, SM_TOTAL);
    cudaFuncSetAttribute(mma_gemmh<false, false, true >, cudaFuncAttributeMaxDynamicSharedMemorySize, SM_TOTAL);
    cudaFuncSetAttribute(mma_gemmh<false, true , false>, cudaFuncAttributeMaxDynamicSharedMemorySize, SM_TOTAL);

    typedef const __half* hfp;
    typedef __half* hfpm;

    convert_h<<<(NROWS * DIN / 4 + 255) / 256, 256>>>((const float4*)obs, (uint2*)obs_f, NROWS * DIN / 4);
    convert_weights<<<(188416 + 255) / 256, 256>>>(
        (const float4*)enc_W, (const float4*)fobs_W,
        (const float4*)W_ih, (const float4*)W_hh,
        (uint2*)ew_f, (uint2*)w23_f, (uint2*)wih_f, (uint2*)whh_f, (uint2*)wc2_f);
    transpose_fw<<<(HD * HD + 255) / 256, 256>>>(fobs_W, (hfpm)fwT_f);
    biases_kernel<<<100, 256>>>(b_ih, b_hh, fobs_b, W_hh, bias2, bias23);

    const dim3 blk(256);
    const int rowBlocks = NROWS / 128;  // 512

    // 0) Wcomb = W_hh @ fobs_W  -> w23_f rows 256..1023   (768x256, K=256)
    mma_gemmh<false, false, true><<<dim3(2, H3 / 128), blk, SM_TOTAL>>>(
        (hfp)whh_f, (hfp)fwT_f, zero_bias, nullptr,
        (hfpm)w23_f + (size_t)HD * HD, HD, HD);
    // 1) e = relu(obs @ enc_W^T + enc_b) -> fp16
    mma_gemmh<true, false, true><<<dim3(2, rowBlocks), blk, SM_TOTAL>>>(
        (hfp)obs_f, (hfp)ew_f, enc_b, nullptr, (hfpm)e_f, DIN, HD);
    // 2+3) [h | gh] = e @ [fobs_W; Wcomb]^T + bias23 -> fp16  (M=1024)
    mma_gemmh<false, false, true><<<dim3(8, rowBlocks), blk, SM_TOTAL>>>(
        (hfp)e_f, (hfp)w23_f, bias23, nullptr, (hfpm)hgh_f, HD, H4);
    // 4) gates k=0 + agent sum -> h1 fp16, S fp16
    gates0S_kernel<<<NB, HD>>>((hfp)hgh_f, b_ih, (hfpm)h1_f, (hfpm)S_f);
    // 5) Sg = S @ W_ih^T (zero bias) -> fp32
    mma_gemmh<false, true, false><<<dim3(6, NB / 128), blk, SM_TOTAL>>>(
        (hfp)S_f, (hfp)wih_f, zero_bias, sg, nullptr, HD, H3);
    // 6) gc2 = h1 @ Wc2^T + bias2 -> fp16   (M=1024)
    mma_gemmh<false, false, true><<<dim3(8, rowBlocks), blk, SM_TOTAL>>>(
        (hfp)h1_f, (hfp)wc2_f, bias2, nullptr, (hfpm)gc2_f, HD, H4);
    // 7) gates k=1 + decoder -> out
    gates1_dec_kernel<<<NROWS / 4, 256>>>((hfp)gc2_f, sg, b_ih, (hfp)h1_f, dec_W, dec_b, out);
}